// round 3
// baseline (speedup 1.0000x reference)
#include <cuda_runtime.h>

// context[b,0,d] = sum_t a[b,t,d]  (softmax over size-1 axis == 1).
// Single-kernel streaming column-sum: grid (B, 4 d-slices), block = 8 t-groups x 32 d-threads.
// Full t-range per block -> reduction completes in smem, no scratch, no 2nd kernel.

#define B_  128
#define TX_ 512
#define D4  128          // D/4 float4 per row
#define DS  4            // d-slices per b (32 float4 each)
#define TG  8            // t-groups per block
#define TPG (TX_ / TG)   // 64 t per group

__global__ __launch_bounds__(256) void colsum_kernel(const float* __restrict__ a,
                                                     float* __restrict__ out) {
    const int b    = blockIdx.x;
    const int ds   = blockIdx.y;
    const int tg   = threadIdx.x >> 5;    // 0..7
    const int dthr = threadIdx.x & 31;    // 0..31

    const float4* base = reinterpret_cast<const float4*>(a)
                         + (size_t)b * TX_ * D4 + ds * 32 + dthr;

    float4 acc = make_float4(0.f, 0.f, 0.f, 0.f);
    const int t0 = tg * TPG;

    #pragma unroll 8
    for (int t = 0; t < TPG; ++t) {
        float4 v = __ldcs(base + (size_t)(t0 + t) * D4);
        acc.x += v.x; acc.y += v.y; acc.z += v.z; acc.w += v.w;
    }

    __shared__ float4 red[TG][32];
    red[tg][dthr] = acc;
    __syncthreads();

    if (tg == 0) {
        float4 s = red[0][dthr];
        #pragma unroll
        for (int g = 1; g < TG; ++g) {
            float4 v = red[g][dthr];
            s.x += v.x; s.y += v.y; s.z += v.z; s.w += v.w;
        }
        reinterpret_cast<float4*>(out)[(size_t)b * D4 + ds * 32 + dthr] = s;
    }
}

extern "C" void kernel_launch(void* const* d_in, const int* in_sizes, int n_in,
                              void* d_out, int out_size) {
    const float* a = (const float*)d_in[0];   // [128, 512, 512] fp32
    float* out = (float*)d_out;               // [128, 1, 512] fp32

    dim3 grid(B_, DS);
    colsum_kernel<<<grid, 256>>>(a, out);
}

// round 4
// speedup vs baseline: 1.0667x; 1.0667x over previous
#include <cuda_runtime.h>

// context[b,0,d] = sum_t a[b,t,d]  (softmax over size-1 axis == 1.0).
// Single launch: 512 blocks stream full 2KB rows; cross-block combine via
// L2-resident partials + monotonic arrival counter (graph-replay safe).

#define B_    128
#define TX_   512
#define D4    128               // D/4 float4 per row
#define SPLIT 4                 // t-splits across blockIdx.y
#define TG    2                 // t-groups per block
#define TPG   (TX_ / (SPLIT * TG))   // 64 t per thread

__device__ float4 g_part[B_ * SPLIT * D4];      // 1 MB, stays in L2
__device__ unsigned int g_cnt[B_];              // zero-init at load; never reset

__global__ __launch_bounds__(256) void colsum_kernel(const float* __restrict__ a,
                                                     float* __restrict__ out) {
    const int b  = blockIdx.x;
    const int s  = blockIdx.y;
    const int tg = threadIdx.x >> 7;     // 0..1
    const int d  = threadIdx.x & 127;    // 0..127 -> full 2KB row coalesced

    const float4* base = reinterpret_cast<const float4*>(a)
                         + (size_t)b * TX_ * D4 + d;
    const int t0 = (s * TG + tg) * TPG;

    float4 acc = make_float4(0.f, 0.f, 0.f, 0.f);
    #pragma unroll 8
    for (int t = 0; t < TPG; ++t) {
        float4 v = base[(size_t)(t0 + t) * D4];
        acc.x += v.x; acc.y += v.y; acc.z += v.z; acc.w += v.w;
    }

    // combine the 2 t-groups in smem
    __shared__ float4 red[D4];
    if (tg == 1) red[d] = acc;
    __syncthreads();
    if (tg == 0) {
        float4 v = red[d];
        acc.x += v.x; acc.y += v.y; acc.z += v.z; acc.w += v.w;
        g_part[(b * SPLIT + s) * D4 + d] = acc;
        __threadfence();                 // release partials
    }
    __syncthreads();

    // last arriving block for this b does the final 4-way reduce from L2
    __shared__ unsigned int is_last;
    if (threadIdx.x == 0) {
        unsigned int old = atomicAdd(&g_cnt[b], 1u);
        is_last = ((old & 3u) == 3u) ? 1u : 0u;   // 4th arrival this call
    }
    __syncthreads();

    if (is_last) {
        __threadfence();                 // acquire partials
        if (threadIdx.x < D4) {
            float4 sum = make_float4(0.f, 0.f, 0.f, 0.f);
            #pragma unroll
            for (int ss = 0; ss < SPLIT; ++ss) {
                float4 v = g_part[(b * SPLIT + ss) * D4 + threadIdx.x];
                sum.x += v.x; sum.y += v.y; sum.z += v.z; sum.w += v.w;
            }
            reinterpret_cast<float4*>(out)[(size_t)b * D4 + threadIdx.x] = sum;
        }
    }
}

extern "C" void kernel_launch(void* const* d_in, const int* in_sizes, int n_in,
                              void* d_out, int out_size) {
    const float* a = (const float*)d_in[0];   // [128, 512, 512] fp32
    float* out = (float*)d_out;               // [128, 1, 512] fp32

    dim3 grid(B_, SPLIT);
    colsum_kernel<<<grid, 256>>>(a, out);
}

// round 6
// speedup vs baseline: 1.0755x; 1.0083x over previous
#include <cuda_runtime.h>

// context[b,0,d] = sum_t a[b,t,d]  (softmax over size-1 axis == 1.0).
// Single launch: 1024 blocks stream full 2KB rows (occ ~86%); cross-block
// combine via L2-resident partials + monotonic arrival counter (replay safe).

#define B_    128
#define TX_   512
#define D4    128               // D/4 float4 per row
#define SPLIT 8                 // t-splits across blockIdx.y
#define TG    2                 // t-groups per block
#define TPG   (TX_ / (SPLIT * TG))   // 32 t per thread

__device__ float4 g_part[B_ * SPLIT * D4];      // 2 MB, stays in L2
__device__ unsigned int g_cnt[B_];              // zero-init at load; never reset

__global__ __launch_bounds__(256) void colsum_kernel(const float* __restrict__ a,
                                                     float* __restrict__ out) {
    const int b  = blockIdx.x;
    const int s  = blockIdx.y;
    const int tg = threadIdx.x >> 7;     // 0..1
    const int d  = threadIdx.x & 127;    // 0..127 -> full 2KB row coalesced

    const float4* base = reinterpret_cast<const float4*>(a)
                         + (size_t)b * TX_ * D4 + d;
    const int t0 = (s * TG + tg) * TPG;

    float4 acc = make_float4(0.f, 0.f, 0.f, 0.f);
    #pragma unroll 8
    for (int t = 0; t < TPG; ++t) {
        float4 v = base[(size_t)(t0 + t) * D4];
        acc.x += v.x; acc.y += v.y; acc.z += v.z; acc.w += v.w;
    }

    // combine the 2 t-groups in smem
    __shared__ float4 red[D4];
    if (tg == 1) red[d] = acc;
    __syncthreads();
    if (tg == 0) {
        float4 v = red[d];
        acc.x += v.x; acc.y += v.y; acc.z += v.z; acc.w += v.w;
        g_part[(b * SPLIT + s) * D4 + d] = acc;
        __threadfence();                 // release partials
    }
    __syncthreads();

    // last arriving block for this b does the final 8-way reduce from L2
    __shared__ unsigned int is_last;
    if (threadIdx.x == 0) {
        unsigned int old = atomicAdd(&g_cnt[b], 1u);
        is_last = ((old & (SPLIT - 1u)) == (SPLIT - 1u)) ? 1u : 0u;
    }
    __syncthreads();

    if (is_last) {
        __threadfence();                 // acquire partials
        if (threadIdx.x < D4) {
            float4 sum = make_float4(0.f, 0.f, 0.f, 0.f);
            #pragma unroll
            for (int ss = 0; ss < SPLIT; ++ss) {
                float4 v = g_part[(b * SPLIT + ss) * D4 + threadIdx.x];
                sum.x += v.x; sum.y += v.y; sum.z += v.z; sum.w += v.w;
            }
            reinterpret_cast<float4*>(out)[(size_t)b * D4 + threadIdx.x] = sum;
        }
    }
}

extern "C" void kernel_launch(void* const* d_in, const int* in_sizes, int n_in,
                              void* d_out, int out_size) {
    const float* a = (const float*)d_in[0];   // [128, 512, 512] fp32
    float* out = (float*)d_out;               // [128, 1, 512] fp32

    dim3 grid(B_, SPLIT);
    colsum_kernel<<<grid, 256>>>(a, out);
}